// round 15
// baseline (speedup 1.0000x reference)
#include <cuda_runtime.h>
#include <cuda_fp16.h>
#include <math.h>
#include <stdint.h>

#define Bb    256
#define HWc   196
#define Ec    1024
#define Hc    1024
#define Lc    128
#define Tc    48
#define FCOUT 1154
#define FCPAD 1280

// ---------------- device-global scratch (allocation-free) ----------------
__device__ float g_m[Bb * Hc];
__device__ float g_base[Bb * 4 * Hc];
__device__ float g_im_part[7][Bb * Ec];                     // mean partials
__device__ __half g_h_hi[2][Bb * Hc], g_h_lo[2][Bb * Hc];   // ping-pong
__device__ __half g_im_hi[Bb * Ec], g_im_lo[Bb * Ec];
__device__ __half g_Whh[4096 * 1024];      // weights: fp16 hi only
__device__ __half g_Wih[4096 * 1024];
__device__ __half g_Wlab[4096 * 128];
__device__ __half g_Wh[1024 * 1024];
__device__ __half g_Wm[1024 * 1024];
__device__ __half g_Wfc[FCPAD * 1024];
__device__ __half g_lab_hi[Bb * Tc * Lc], g_lab_lo[Bb * Tc * Lc];

// ---------------- helpers ----------------
__device__ __forceinline__ float sigmoidf_(float x) { return 1.0f / (1.0f + expf(-x)); }

__device__ __forceinline__ void f16split(float v, __half& h, __half& l) {
    h = __float2half_rn(v);
    l = __float2half_rn(v - __half2float(h));
}
__device__ __forceinline__ uint32_t smem_u32(const void* p) {
    return (uint32_t)__cvta_generic_to_shared(p);
}
__device__ __forceinline__ void cpasync16(uint32_t s, const void* g) {
    asm volatile("cp.async.cg.shared.global [%0], [%1], 16;\n" :: "r"(s), "l"(g) : "memory");
}
#define CP_COMMIT() asm volatile("cp.async.commit_group;\n" ::: "memory")
#define CP_WAIT2()  asm volatile("cp.async.wait_group 2;\n" ::: "memory")

__device__ __forceinline__ void ldsm4(uint32_t* r, uint32_t a) {
    asm volatile("ldmatrix.sync.aligned.m8n8.x4.shared.b16 {%0,%1,%2,%3}, [%4];"
        : "=r"(r[0]), "=r"(r[1]), "=r"(r[2]), "=r"(r[3]) : "r"(a));
}
__device__ __forceinline__ void ldsm2(uint32_t* r, uint32_t a) {
    asm volatile("ldmatrix.sync.aligned.m8n8.x2.shared.b16 {%0,%1}, [%2];"
        : "=r"(r[0]), "=r"(r[1]) : "r"(a));
}
__device__ __forceinline__ void mma_f16(float* c, const uint32_t* a, const uint32_t* b) {
    asm volatile("mma.sync.aligned.m16n8k16.row.col.f32.f16.f16.f32 "
        "{%0,%1,%2,%3}, {%4,%5,%6,%7}, {%8,%9}, {%0,%1,%2,%3};"
        : "+f"(c[0]), "+f"(c[1]), "+f"(c[2]), "+f"(c[3])
        : "r"(a[0]), "r"(a[1]), "r"(a[2]), "r"(a[3]), "r"(b[0]), "r"(b[1]));
}

// ---------------- K0: zero the whole output (dead regions stay 0) --------
__global__ __launch_bounds__(256) void zero_out(float4* __restrict__ o, int n4) {
    int idx = blockIdx.x * 256 + threadIdx.x;
    if (idx < n4) o[idx] = make_float4(0.f, 0.f, 0.f, 0.f);
}

// ---------------- K1a: mean partial sums (grid 256 x 7) ------------------
__global__ __launch_bounds__(256) void mean_part(const float* __restrict__ img) {
    int b = blockIdx.x, chunk = blockIdx.y, e4 = threadIdx.x;
    const float4* p = (const float4*)img + ((size_t)b * HWc + chunk * 28) * 256 + e4;
    float4 s = make_float4(0.f, 0.f, 0.f, 0.f);
    #pragma unroll 4
    for (int hw = 0; hw < 28; ++hw) {
        float4 v = p[(size_t)hw * 256];
        s.x += v.x; s.y += v.y; s.z += v.z; s.w += v.w;
    }
    *(float4*)&g_im_part[chunk][(b << 10) + e4 * 4] = s;
}

// ---------------- K1b: mean reduce + fp16 split --------------------------
__global__ __launch_bounds__(256) void mean_reduce() {
    int idx = blockIdx.x * 256 + threadIdx.x;     // B*E/4
    float4 s = make_float4(0.f, 0.f, 0.f, 0.f);
    #pragma unroll
    for (int c = 0; c < 7; ++c) {
        float4 v = *(const float4*)&g_im_part[c][idx * 4];
        s.x += v.x; s.y += v.y; s.z += v.z; s.w += v.w;
    }
    const float inv = 1.0f / HWc;
    float vals[4] = {s.x * inv, s.y * inv, s.z * inv, s.w * inv};
    #pragma unroll
    for (int j = 0; j < 4; ++j) {
        __half h, l;
        f16split(vals[j], h, l);
        g_im_hi[idx * 4 + j] = h;
        g_im_lo[idx * 4 + j] = l;
    }
}

// ---------------- K2: ONE fused fp32 -> fp16 split over all segments -----
__device__ __forceinline__ void do_split4(
    const float* __restrict__ in, int ld, int c0, int cs,
    int rows_valid, int idx, __half* __restrict__ ph, __half* __restrict__ pl)
{
    int r = idx >> cs, c4 = idx & ((1 << cs) - 1);
    float4 v = make_float4(0.f, 0.f, 0.f, 0.f);
    if (r < rows_valid) v = *(const float4*)(in + (size_t)r * ld + c0 + c4 * 4);
    float vv[4] = {v.x, v.y, v.z, v.w};
    __half hi[4], lo[4];
    #pragma unroll
    for (int j = 0; j < 4; ++j) f16split(vv[j], hi[j], lo[j]);
    __half2* dh = (__half2*)(ph + (size_t)idx * 4);
    __half2 a, b;
    a.x = hi[0]; a.y = hi[1]; b.x = hi[2]; b.y = hi[3];
    dh[0] = a; dh[1] = b;
    if (pl) {
        __half2* dl = (__half2*)(pl + (size_t)idx * 4);
        a.x = lo[0]; a.y = lo[1]; b.x = lo[2]; b.y = lo[3];
        dl[0] = a; dl[1] = b;
    }
}

// segment sizes in float4 units
#define S_WH   262144
#define S_WM   262144
#define S_WIH  1048576
#define S_WLAB 131072
#define S_WHH  1048576
#define S_WFC  327680     // FCPAD*1024/4
#define S_LAB  393216     // Bb*Tc*Lc/4
#define C0 (S_WH)
#define C1 (C0 + S_WM)
#define C2 (C1 + S_WIH)
#define C3 (C2 + S_WLAB)
#define C4 (C3 + S_WHH)
#define C5 (C4 + S_WFC)
#define C6 (C5 + S_LAB)

__global__ __launch_bounds__(256) void split_all(
    const float* __restrict__ W_h,  const float* __restrict__ W_m,
    const float* __restrict__ W_ih, const float* __restrict__ W_hh,
    const float* __restrict__ W_fc, const float* __restrict__ label)
{
    int idx = blockIdx.x * 256 + threadIdx.x;
    if (idx < C0)      do_split4(W_h,  1024, 0,    8, 1024,  idx,      g_Wh,   nullptr);
    else if (idx < C1) do_split4(W_m,  1024, 0,    8, 1024,  idx - C0, g_Wm,   nullptr);
    else if (idx < C2) do_split4(W_ih, 1152, 0,    8, 4096,  idx - C1, g_Wih,  nullptr);
    else if (idx < C3) do_split4(W_ih, 1152, 1024, 5, 4096,  idx - C2, g_Wlab, nullptr);
    else if (idx < C4) do_split4(W_hh, 1024, 0,    8, 4096,  idx - C3, g_Whh,  nullptr);
    else if (idx < C5) do_split4(W_fc, 1024, 0,    8, FCOUT, idx - C4, g_Wfc,  nullptr);
    else if (idx < C6) do_split4(label, Lc,  0,    5, Bb*Tc, idx - C5, g_lab_hi, g_lab_lo);
}

// ---------------- K3: setup GEMMs (mma.sync fp16 2-term) -----------------
// MODE 1: base = im@Wih^T + b_ih + b_hh ; MODE 2: h0 -> g_h[0] ; MODE 3: m0
// Stage (15360 B x4): Ahi@0(5120) Alo@5120 Bhi@10240(5120)
template<int MODE>
__global__ void __launch_bounds__(128, 3) mma_big(
    const float* __restrict__ bias1, const float* __restrict__ bias2)
{
    constexpr int NIT = 1024 / 32;
    extern __shared__ char smem[];
    const uint32_t smb = smem_u32(smem);

    const int tid = threadIdx.x, lane = tid & 31, w = tid >> 5;
    const int bm0 = blockIdx.y * 64, bn0 = blockIdx.x * 64;

    float acc[2][4][4];
    #pragma unroll
    for (int a = 0; a < 2; ++a)
        #pragma unroll
        for (int b = 0; b < 4; ++b)
            #pragma unroll
            for (int c = 0; c < 4; ++c) acc[a][b][c] = 0.0f;

    auto load_stage = [&](int st, int k0) {
        uint32_t sb = smb + (uint32_t)st * 15360u;
        #pragma unroll
        for (int s = 0; s < 2; ++s) {                 // A hi+lo
            int slot = tid + s * 128;
            int r = slot >> 2, ch = slot & 3, k = k0 + ch * 8;
            size_t off = (size_t)(bm0 + r) * 1024 + k;
            uint32_t so = (uint32_t)(r * 80 + ch * 16);
            cpasync16(sb + so, g_im_hi + off);
            cpasync16(sb + 5120u + so, g_im_lo + off);
        }
        #pragma unroll
        for (int s = 0; s < 2; ++s) {                 // B hi only
            int slot = tid + s * 128;
            int r = slot >> 2, ch = slot & 3, k = k0 + ch * 8;
            size_t off = (size_t)(bn0 + r) * 1024 + k;
            const __half* gh;
            if      (MODE == 1) gh = g_Wih + off;
            else if (MODE == 2) gh = g_Wh + off;
            else                gh = g_Wm + off;
            uint32_t so = (uint32_t)(r * 80 + ch * 16);
            cpasync16(sb + 10240u + so, gh);
        }
    };

    load_stage(0, 0);  CP_COMMIT();
    load_stage(1, 32); CP_COMMIT();

    const uint32_t aOff = (uint32_t)(((w >> 1) * 32 + (lane & 15)) * 80 + (lane >> 4) * 16);
    const uint32_t bOff = (uint32_t)(((w & 1) * 32 + (lane & 7)) * 80 + ((lane >> 3) & 1) * 16);

    for (int it = 0; it < NIT; ++it) {
        if (it + 2 < NIT) load_stage((it + 2) & 3, (it + 2) * 32);
        CP_COMMIT();
        CP_WAIT2();
        __syncthreads();
        uint32_t sb = smb + (uint32_t)(it & 3) * 15360u;
        #pragma unroll
        for (int kh = 0; kh < 2; ++kh) {
            uint32_t afh[2][4], afl[2][4], bfh[4][2];
            #pragma unroll
            for (int mi = 0; mi < 2; ++mi) {
                uint32_t ad = sb + aOff + (uint32_t)(mi * 1280 + kh * 32);
                ldsm4(afh[mi], ad);
                ldsm4(afl[mi], ad + 5120u);
            }
            #pragma unroll
            for (int ni = 0; ni < 4; ++ni) {
                uint32_t bd = sb + 10240u + bOff + (uint32_t)(ni * 640 + kh * 32);
                ldsm2(bfh[ni], bd);
            }
            #pragma unroll
            for (int mi = 0; mi < 2; ++mi)
                #pragma unroll
                for (int ni = 0; ni < 4; ++ni)
                    mma_f16(acc[mi][ni], afh[mi], bfh[ni]);
            #pragma unroll
            for (int mi = 0; mi < 2; ++mi)
                #pragma unroll
                for (int ni = 0; ni < 4; ++ni)
                    mma_f16(acc[mi][ni], afl[mi], bfh[ni]);
        }
    }

    #pragma unroll
    for (int mi = 0; mi < 2; ++mi) {
        int r0 = bm0 + (w >> 1) * 32 + mi * 16 + (lane >> 2);
        #pragma unroll
        for (int ni = 0; ni < 4; ++ni) {
            int c0 = bn0 + (w & 1) * 32 + ni * 8 + (lane & 3) * 2;
            float* a = acc[mi][ni];
            if (MODE == 1) {
                float b0 = bias1[c0] + bias2[c0], b1 = bias1[c0 + 1] + bias2[c0 + 1];
                *(float2*)&g_base[(size_t)r0 * 4096 + c0]       = make_float2(a[0] + b0, a[1] + b1);
                *(float2*)&g_base[(size_t)(r0 + 8) * 4096 + c0] = make_float2(a[2] + b0, a[3] + b1);
            } else {
                float b0 = bias1[c0], b1 = bias1[c0 + 1];
                float v0 = tanhf(a[0] + b0), v1 = tanhf(a[1] + b1);
                float v2 = tanhf(a[2] + b0), v3 = tanhf(a[3] + b1);
                if (MODE == 2) {
                    __half h0, l0, h1, l1;
                    __half2 hh, ll;
                    f16split(v0, h0, l0); f16split(v1, h1, l1);
                    hh.x = h0; hh.y = h1; ll.x = l0; ll.y = l1;
                    *(__half2*)&g_h_hi[0][(size_t)r0 * 1024 + c0] = hh;
                    *(__half2*)&g_h_lo[0][(size_t)r0 * 1024 + c0] = ll;
                    f16split(v2, h0, l0); f16split(v3, h1, l1);
                    hh.x = h0; hh.y = h1; ll.x = l0; ll.y = l1;
                    *(__half2*)&g_h_hi[0][(size_t)(r0 + 8) * 1024 + c0] = hh;
                    *(__half2*)&g_h_lo[0][(size_t)(r0 + 8) * 1024 + c0] = ll;
                } else {
                    g_m[(size_t)r0 * 1024 + c0]           = v0;
                    g_m[(size_t)r0 * 1024 + c0 + 1]       = v1;
                    g_m[(size_t)(r0 + 8) * 1024 + c0]     = v2;
                    g_m[(size_t)(r0 + 8) * 1024 + c0 + 1] = v3;
                }
            }
        }
    }
}

// ---------------- K4: fused step kernel ----------------------------------
// grid (83, 4), 128 threads, 3 CTAs/SM (smem 61440). One launch per step t:
//   x < 64 : GATES role, step t. Tile 64 rows x [i|f|g|o]x16 h-cols, K=1152.
//            2-term (A hi+lo x B hi) — feeds the recurrence, keep accurate.
//   x >= 64: FC role, step tf = t-1. Tile 64 rows x 64 cols, K=1024.
//            1-term (A hi x B hi) — one-shot output, error ~3.4e-4 total.
// Both roles read h[t&1]; gates write h[(t+1)&1] + m -> race-free.
// Dead blocks return immediately (output pre-zeroed by zero_out).
__global__ void __launch_bounds__(128, 3) step_fused(
    const float* __restrict__ bfc, const int* __restrict__ length,
    float* __restrict__ out, int t)
{
    extern __shared__ char smem[];
    const uint32_t smb = smem_u32(smem);
    const int tid = threadIdx.x, lane = tid & 31, w = tid >> 5;
    const int bm0 = blockIdx.y * 64;
    const bool gates_role = (blockIdx.x < 64);
    const int tf = t - 1;

    int bn0h = 0, bn0f = 0, nit;
    if (gates_role) {
        if (t >= Tc) return;
        if (t >= length[bm0]) return;        // block fully dead (desc-sorted)
        bn0h = blockIdx.x * 16;
        nit = 36;
    } else {
        if (tf < 0) return;
        if (tf >= length[bm0]) return;       // dead: output pre-zeroed
        bn0f = (blockIdx.x - 64) * 64;
        nit = 32;
    }

    const __half* h_in_hi = g_h_hi[t & 1];
    const __half* h_in_lo = g_h_lo[t & 1];

    float acc[2][4][4];
    #pragma unroll
    for (int a = 0; a < 2; ++a)
        #pragma unroll
        for (int b = 0; b < 4; ++b)
            #pragma unroll
            for (int c = 0; c < 4; ++c) acc[a][b][c] = 0.0f;

    auto load_stage = [&](int st, int k0) {
        uint32_t sb = smb + (uint32_t)st * 15360u;
        #pragma unroll
        for (int s = 0; s < 2; ++s) {                 // A hi (+lo for gates)
            int slot = tid + s * 128;
            int r = slot >> 2, ch = slot & 3, k = k0 + ch * 8;
            const __half *ah, *al;
            if (gates_role && k >= 1024) {
                size_t off = ((size_t)(bm0 + r) * Tc + t) * Lc + (k - 1024);
                ah = g_lab_hi + off; al = g_lab_lo + off;
            } else {
                size_t off = (size_t)(bm0 + r) * 1024 + k;
                ah = h_in_hi + off; al = h_in_lo + off;
            }
            uint32_t so = (uint32_t)(r * 80 + ch * 16);
            cpasync16(sb + so, ah);
            if (gates_role) cpasync16(sb + 5120u + so, al);
        }
        #pragma unroll
        for (int s = 0; s < 2; ++s) {                 // B hi only
            int slot = tid + s * 128;
            int r = slot >> 2, ch = slot & 3, k = k0 + ch * 8;
            const __half* bh;
            if (gates_role) {
                int grow = (r >> 4) * 1024 + bn0h + (r & 15);
                if (k >= 1024) bh = g_Wlab + (size_t)grow * 128 + (k - 1024);
                else           bh = g_Whh + (size_t)grow * 1024 + k;
            } else {
                bh = g_Wfc + (size_t)(bn0f + r) * 1024 + k;
            }
            uint32_t so = (uint32_t)(r * 80 + ch * 16);
            cpasync16(sb + 10240u + so, bh);
        }
    };

    load_stage(0, 0);  CP_COMMIT();
    load_stage(1, 32); CP_COMMIT();

    const uint32_t aOff = (uint32_t)(((w >> 1) * 32 + (lane & 15)) * 80 + (lane >> 4) * 16);
    const uint32_t bOff = (uint32_t)(((w & 1) * 32 + (lane & 7)) * 80 + ((lane >> 3) & 1) * 16);

    for (int it = 0; it < nit; ++it) {
        if (it + 2 < nit) load_stage((it + 2) & 3, (it + 2) * 32);
        CP_COMMIT();
        CP_WAIT2();
        __syncthreads();
        uint32_t sb = smb + (uint32_t)(it & 3) * 15360u;
        #pragma unroll
        for (int kh = 0; kh < 2; ++kh) {
            uint32_t afh[2][4], afl[2][4], bfh[4][2];
            #pragma unroll
            for (int mi = 0; mi < 2; ++mi) {
                uint32_t ad = sb + aOff + (uint32_t)(mi * 1280 + kh * 32);
                ldsm4(afh[mi], ad);
                if (gates_role) ldsm4(afl[mi], ad + 5120u);
            }
            #pragma unroll
            for (int ni = 0; ni < 4; ++ni) {
                uint32_t bd = sb + 10240u + bOff + (uint32_t)(ni * 640 + kh * 32);
                ldsm2(bfh[ni], bd);
            }
            #pragma unroll
            for (int mi = 0; mi < 2; ++mi)
                #pragma unroll
                for (int ni = 0; ni < 4; ++ni)
                    mma_f16(acc[mi][ni], afh[mi], bfh[ni]);
            if (gates_role) {
                #pragma unroll
                for (int mi = 0; mi < 2; ++mi)
                    #pragma unroll
                    for (int ni = 0; ni < 4; ++ni)
                        mma_f16(acc[mi][ni], afl[mi], bfh[ni]);
            }
        }
    }
    __syncthreads();   // close skew before smem reuse (gates staging)

    if (gates_role) {
        // ---- stage 64x64 gate tile to smem (stride 68 floats) ----
        float* stg = (float*)smem;
        #pragma unroll
        for (int mi = 0; mi < 2; ++mi) {
            int r0 = (w >> 1) * 32 + mi * 16 + (lane >> 2);
            #pragma unroll
            for (int ni = 0; ni < 4; ++ni) {
                int c0 = (w & 1) * 32 + ni * 8 + (lane & 3) * 2;
                float* a = acc[mi][ni];
                *(float2*)&stg[r0 * 68 + c0]       = make_float2(a[0], a[1]);
                *(float2*)&stg[(r0 + 8) * 68 + c0] = make_float2(a[2], a[3]);
            }
        }
        __syncthreads();

        // ---- LSTM cell update (h ping-pong write) ----
        __half* h_out_hi = g_h_hi[(t + 1) & 1];
        __half* h_out_lo = g_h_lo[(t + 1) & 1];
        int nl = tid & 15;
        int rg = tid >> 4;
        int n = bn0h + nl;
        #pragma unroll
        for (int j = 0; j < 8; ++j) {
            int r = rg * 8 + j;
            int row = bm0 + r;
            float iv = stg[r * 68 + nl];
            float fv = stg[r * 68 + 16 + nl];
            float gv = stg[r * 68 + 32 + nl];
            float ov = stg[r * 68 + 48 + nl];
            size_t bidx = (size_t)row * 4096;
            iv += g_base[bidx + n];
            fv += g_base[bidx + 1024 + n];
            gv += g_base[bidx + 2048 + n];
            ov += g_base[bidx + 3072 + n];
            size_t hidx = (size_t)row * 1024 + n;
            float m = sigmoidf_(fv) * g_m[hidx] + sigmoidf_(iv) * tanhf(gv);
            g_m[hidx] = m;
            float h = sigmoidf_(ov) * tanhf(m);
            __half hh, hl;
            f16split(h, hh, hl);
            h_out_hi[hidx] = hh;
            h_out_lo[hidx] = hl;
        }
    } else {
        // ---- fc epilogue for step tf ----
        float* lab  = out;
        float* top  = out  + (size_t)Bb * Tc * Lc;
        float* temp = top  + (size_t)Bb * Tc * Hc;
        float* stop = temp + (size_t)Bb * Tc;
        #pragma unroll
        for (int mi = 0; mi < 2; ++mi) {
            int r0 = bm0 + (w >> 1) * 32 + mi * 16 + (lane >> 2);
            #pragma unroll
            for (int ni = 0; ni < 4; ++ni) {
                int c0 = bn0f + (w & 1) * 32 + ni * 8 + (lane & 3) * 2;
                float* a = acc[mi][ni];
                #pragma unroll
                for (int half = 0; half < 2; ++half) {
                    int r = r0 + half * 8;
                    float mask = (tf < length[r]) ? 1.0f : 0.0f;
                    size_t bt = (size_t)r * Tc + tf;
                    #pragma unroll
                    for (int j = 0; j < 2; ++j) {
                        int n = c0 + j;
                        if (n < FCOUT) {
                            float v = fmaxf(a[half * 2 + j] + bfc[n], 0.0f);
                            if (n < Lc)            lab[bt * Lc + n]        = v * mask;
                            else if (n < Lc + Hc)  top[bt * Hc + (n - Lc)] = v * mask;
                            else if (n == Lc + Hc) temp[bt]                = expf(v) * mask;
                            else                   stop[bt]                = sigmoidf_(v) * mask;
                        }
                    }
                }
            }
        }
    }
}

// ---------------- launch -------------------------------------------------
#define SMEM_MMA 61440

extern "C" void kernel_launch(void* const* d_in, const int* in_sizes, int n_in,
                              void* d_out, int out_size)
{
    const float* image  = (const float*)d_in[0];
    const float* label  = (const float*)d_in[1];
    const int*   length = (const int*)  d_in[2];
    const float* W_h    = (const float*)d_in[3];
    const float* b_h    = (const float*)d_in[4];
    const float* W_m    = (const float*)d_in[5];
    const float* b_m    = (const float*)d_in[6];
    const float* W_ih   = (const float*)d_in[7];
    const float* W_hh   = (const float*)d_in[8];
    const float* b_ih   = (const float*)d_in[9];
    const float* b_hh   = (const float*)d_in[10];
    const float* W_fc   = (const float*)d_in[11];
    const float* b_fc   = (const float*)d_in[12];
    float* out = (float*)d_out;

    static bool attr_done = false;
    if (!attr_done) {
        cudaFuncSetAttribute(mma_big<1>, cudaFuncAttributeMaxDynamicSharedMemorySize, SMEM_MMA);
        cudaFuncSetAttribute(mma_big<2>, cudaFuncAttributeMaxDynamicSharedMemorySize, SMEM_MMA);
        cudaFuncSetAttribute(mma_big<3>, cudaFuncAttributeMaxDynamicSharedMemorySize, SMEM_MMA);
        cudaFuncSetAttribute(step_fused, cudaFuncAttributeMaxDynamicSharedMemorySize, SMEM_MMA);
        attr_done = true;
    }

    int n4 = out_size / 4;
    zero_out<<<(n4 + 255) / 256, 256>>>((float4*)out, n4);
    mean_part<<<dim3(Bb, 7), 256>>>(image);
    mean_reduce<<<(Bb * Ec / 4) / 256, 256>>>();
    split_all<<<(C6 + 255) / 256, 256>>>(W_h, W_m, W_ih, W_hh, W_fc, label);

    mma_big<1><<<dim3(64, 4), 128, SMEM_MMA>>>(b_ih, b_hh);
    mma_big<2><<<dim3(16, 4), 128, SMEM_MMA>>>(b_h, nullptr);
    mma_big<3><<<dim3(16, 4), 128, SMEM_MMA>>>(b_m, nullptr);

    // step t: gates_t (x<64) + fc_{t-1} (x in 64..82); t=Tc runs fc_{Tc-1} only
    for (int t = 0; t <= Tc; ++t) {
        step_fused<<<dim3(83, 4), 128, SMEM_MMA>>>(b_fc, length, out, t);
    }
}

// round 16
// speedup vs baseline: 1.0689x; 1.0689x over previous
#include <cuda_runtime.h>
#include <cuda_fp16.h>
#include <math.h>
#include <stdint.h>

#define Bb    256
#define HWc   196
#define Ec    1024
#define Hc    1024
#define Lc    128
#define Tc    48
#define FCOUT 1154
#define FCPAD 1280

// ---------------- device-global scratch (allocation-free) ----------------
__device__ float g_m[Bb * Hc];
__device__ float g_base[Bb * 4 * Hc];
__device__ float g_im_part[7][Bb * Ec];                     // mean partials
__device__ __half g_h_hi[2][Bb * Hc], g_h_lo[2][Bb * Hc];   // ping-pong
__device__ __half g_im_hi[Bb * Ec], g_im_lo[Bb * Ec];
__device__ __half g_Whh[4096 * 1024];      // weights: fp16 hi only
__device__ __half g_Wih[4096 * 1024];
__device__ __half g_Wlab[4096 * 128];
__device__ __half g_Wh[1024 * 1024];
__device__ __half g_Wm[1024 * 1024];
__device__ __half g_Wfc[FCPAD * 1024];
__device__ __half g_lab_hi[Bb * Tc * Lc], g_lab_lo[Bb * Tc * Lc];

// ---------------- helpers ----------------
__device__ __forceinline__ float sigmoidf_(float x) { return 1.0f / (1.0f + expf(-x)); }

__device__ __forceinline__ void f16split(float v, __half& h, __half& l) {
    h = __float2half_rn(v);
    l = __float2half_rn(v - __half2float(h));
}
__device__ __forceinline__ uint32_t smem_u32(const void* p) {
    return (uint32_t)__cvta_generic_to_shared(p);
}
__device__ __forceinline__ void cpasync16(uint32_t s, const void* g) {
    asm volatile("cp.async.cg.shared.global [%0], [%1], 16;\n" :: "r"(s), "l"(g) : "memory");
}
#define CP_COMMIT() asm volatile("cp.async.commit_group;\n" ::: "memory")
#define CP_WAIT2()  asm volatile("cp.async.wait_group 2;\n" ::: "memory")

__device__ __forceinline__ void ldsm4(uint32_t* r, uint32_t a) {
    asm volatile("ldmatrix.sync.aligned.m8n8.x4.shared.b16 {%0,%1,%2,%3}, [%4];"
        : "=r"(r[0]), "=r"(r[1]), "=r"(r[2]), "=r"(r[3]) : "r"(a));
}
__device__ __forceinline__ void ldsm2(uint32_t* r, uint32_t a) {
    asm volatile("ldmatrix.sync.aligned.m8n8.x2.shared.b16 {%0,%1}, [%2];"
        : "=r"(r[0]), "=r"(r[1]) : "r"(a));
}
__device__ __forceinline__ void mma_f16(float* c, const uint32_t* a, const uint32_t* b) {
    asm volatile("mma.sync.aligned.m16n8k16.row.col.f32.f16.f16.f32 "
        "{%0,%1,%2,%3}, {%4,%5,%6,%7}, {%8,%9}, {%0,%1,%2,%3};"
        : "+f"(c[0]), "+f"(c[1]), "+f"(c[2]), "+f"(c[3])
        : "r"(a[0]), "r"(a[1]), "r"(a[2]), "r"(a[3]), "r"(b[0]), "r"(b[1]));
}

// ---------------- K0: zero the whole output (dead regions stay 0) --------
__global__ __launch_bounds__(256) void zero_out(float4* __restrict__ o, int n4) {
    int idx = blockIdx.x * 256 + threadIdx.x;
    if (idx < n4) o[idx] = make_float4(0.f, 0.f, 0.f, 0.f);
}

// ---------------- K1a: mean partial sums (grid 256 x 7) ------------------
__global__ __launch_bounds__(256) void mean_part(const float* __restrict__ img) {
    int b = blockIdx.x, chunk = blockIdx.y, e4 = threadIdx.x;
    const float4* p = (const float4*)img + ((size_t)b * HWc + chunk * 28) * 256 + e4;
    float4 s = make_float4(0.f, 0.f, 0.f, 0.f);
    #pragma unroll 4
    for (int hw = 0; hw < 28; ++hw) {
        float4 v = p[(size_t)hw * 256];
        s.x += v.x; s.y += v.y; s.z += v.z; s.w += v.w;
    }
    *(float4*)&g_im_part[chunk][(b << 10) + e4 * 4] = s;
}

// ---------------- K1b: mean reduce + fp16 split --------------------------
__global__ __launch_bounds__(256) void mean_reduce() {
    int idx = blockIdx.x * 256 + threadIdx.x;     // B*E/4
    float4 s = make_float4(0.f, 0.f, 0.f, 0.f);
    #pragma unroll
    for (int c = 0; c < 7; ++c) {
        float4 v = *(const float4*)&g_im_part[c][idx * 4];
        s.x += v.x; s.y += v.y; s.z += v.z; s.w += v.w;
    }
    const float inv = 1.0f / HWc;
    float vals[4] = {s.x * inv, s.y * inv, s.z * inv, s.w * inv};
    #pragma unroll
    for (int j = 0; j < 4; ++j) {
        __half h, l;
        f16split(vals[j], h, l);
        g_im_hi[idx * 4 + j] = h;
        g_im_lo[idx * 4 + j] = l;
    }
}

// ---------------- K2: ONE fused fp32 -> fp16 split over all segments -----
__device__ __forceinline__ void do_split4(
    const float* __restrict__ in, int ld, int c0, int cs,
    int rows_valid, int idx, __half* __restrict__ ph, __half* __restrict__ pl)
{
    int r = idx >> cs, c4 = idx & ((1 << cs) - 1);
    float4 v = make_float4(0.f, 0.f, 0.f, 0.f);
    if (r < rows_valid) v = *(const float4*)(in + (size_t)r * ld + c0 + c4 * 4);
    float vv[4] = {v.x, v.y, v.z, v.w};
    __half hi[4], lo[4];
    #pragma unroll
    for (int j = 0; j < 4; ++j) f16split(vv[j], hi[j], lo[j]);
    __half2* dh = (__half2*)(ph + (size_t)idx * 4);
    __half2 a, b;
    a.x = hi[0]; a.y = hi[1]; b.x = hi[2]; b.y = hi[3];
    dh[0] = a; dh[1] = b;
    if (pl) {
        __half2* dl = (__half2*)(pl + (size_t)idx * 4);
        a.x = lo[0]; a.y = lo[1]; b.x = lo[2]; b.y = lo[3];
        dl[0] = a; dl[1] = b;
    }
}

// segment sizes in float4 units
#define S_WH   262144
#define S_WM   262144
#define S_WIH  1048576
#define S_WLAB 131072
#define S_WHH  1048576
#define S_WFC  327680     // FCPAD*1024/4
#define S_LAB  393216     // Bb*Tc*Lc/4
#define C0 (S_WH)
#define C1 (C0 + S_WM)
#define C2 (C1 + S_WIH)
#define C3 (C2 + S_WLAB)
#define C4 (C3 + S_WHH)
#define C5 (C4 + S_WFC)
#define C6 (C5 + S_LAB)

__global__ __launch_bounds__(256) void split_all(
    const float* __restrict__ W_h,  const float* __restrict__ W_m,
    const float* __restrict__ W_ih, const float* __restrict__ W_hh,
    const float* __restrict__ W_fc, const float* __restrict__ label)
{
    int idx = blockIdx.x * 256 + threadIdx.x;
    if (idx < C0)      do_split4(W_h,  1024, 0,    8, 1024,  idx,      g_Wh,   nullptr);
    else if (idx < C1) do_split4(W_m,  1024, 0,    8, 1024,  idx - C0, g_Wm,   nullptr);
    else if (idx < C2) do_split4(W_ih, 1152, 0,    8, 4096,  idx - C1, g_Wih,  nullptr);
    else if (idx < C3) do_split4(W_ih, 1152, 1024, 5, 4096,  idx - C2, g_Wlab, nullptr);
    else if (idx < C4) do_split4(W_hh, 1024, 0,    8, 4096,  idx - C3, g_Whh,  nullptr);
    else if (idx < C5) do_split4(W_fc, 1024, 0,    8, FCOUT, idx - C4, g_Wfc,  nullptr);
    else if (idx < C6) do_split4(label, Lc,  0,    5, Bb*Tc, idx - C5, g_lab_hi, g_lab_lo);
}

// ---------------- K3: setup GEMMs (mma.sync fp16 2-term) -----------------
// MODE 1: base = im@Wih^T + b_ih + b_hh ; MODE 2: h0 -> g_h[0] ; MODE 3: m0
// Stage (15360 B x4): Ahi@0(5120) Alo@5120 Bhi@10240(5120)
template<int MODE>
__global__ void __launch_bounds__(128, 3) mma_big(
    const float* __restrict__ bias1, const float* __restrict__ bias2)
{
    constexpr int NIT = 1024 / 32;
    extern __shared__ char smem[];
    const uint32_t smb = smem_u32(smem);

    const int tid = threadIdx.x, lane = tid & 31, w = tid >> 5;
    const int bm0 = blockIdx.y * 64, bn0 = blockIdx.x * 64;

    float acc[2][4][4];
    #pragma unroll
    for (int a = 0; a < 2; ++a)
        #pragma unroll
        for (int b = 0; b < 4; ++b)
            #pragma unroll
            for (int c = 0; c < 4; ++c) acc[a][b][c] = 0.0f;

    auto load_stage = [&](int st, int k0) {
        uint32_t sb = smb + (uint32_t)st * 15360u;
        #pragma unroll
        for (int s = 0; s < 2; ++s) {                 // A hi+lo
            int slot = tid + s * 128;
            int r = slot >> 2, ch = slot & 3, k = k0 + ch * 8;
            size_t off = (size_t)(bm0 + r) * 1024 + k;
            uint32_t so = (uint32_t)(r * 80 + ch * 16);
            cpasync16(sb + so, g_im_hi + off);
            cpasync16(sb + 5120u + so, g_im_lo + off);
        }
        #pragma unroll
        for (int s = 0; s < 2; ++s) {                 // B hi only
            int slot = tid + s * 128;
            int r = slot >> 2, ch = slot & 3, k = k0 + ch * 8;
            size_t off = (size_t)(bn0 + r) * 1024 + k;
            const __half* gh;
            if      (MODE == 1) gh = g_Wih + off;
            else if (MODE == 2) gh = g_Wh + off;
            else                gh = g_Wm + off;
            uint32_t so = (uint32_t)(r * 80 + ch * 16);
            cpasync16(sb + 10240u + so, gh);
        }
    };

    load_stage(0, 0);  CP_COMMIT();
    load_stage(1, 32); CP_COMMIT();

    const uint32_t aOff = (uint32_t)(((w >> 1) * 32 + (lane & 15)) * 80 + (lane >> 4) * 16);
    const uint32_t bOff = (uint32_t)(((w & 1) * 32 + (lane & 7)) * 80 + ((lane >> 3) & 1) * 16);

    for (int it = 0; it < NIT; ++it) {
        if (it + 2 < NIT) load_stage((it + 2) & 3, (it + 2) * 32);
        CP_COMMIT();
        CP_WAIT2();
        __syncthreads();
        uint32_t sb = smb + (uint32_t)(it & 3) * 15360u;
        #pragma unroll
        for (int kh = 0; kh < 2; ++kh) {
            uint32_t afh[2][4], afl[2][4], bfh[4][2];
            #pragma unroll
            for (int mi = 0; mi < 2; ++mi) {
                uint32_t ad = sb + aOff + (uint32_t)(mi * 1280 + kh * 32);
                ldsm4(afh[mi], ad);
                ldsm4(afl[mi], ad + 5120u);
            }
            #pragma unroll
            for (int ni = 0; ni < 4; ++ni) {
                uint32_t bd = sb + 10240u + bOff + (uint32_t)(ni * 640 + kh * 32);
                ldsm2(bfh[ni], bd);
            }
            #pragma unroll
            for (int mi = 0; mi < 2; ++mi)
                #pragma unroll
                for (int ni = 0; ni < 4; ++ni)
                    mma_f16(acc[mi][ni], afh[mi], bfh[ni]);
            #pragma unroll
            for (int mi = 0; mi < 2; ++mi)
                #pragma unroll
                for (int ni = 0; ni < 4; ++ni)
                    mma_f16(acc[mi][ni], afl[mi], bfh[ni]);
        }
    }

    #pragma unroll
    for (int mi = 0; mi < 2; ++mi) {
        int r0 = bm0 + (w >> 1) * 32 + mi * 16 + (lane >> 2);
        #pragma unroll
        for (int ni = 0; ni < 4; ++ni) {
            int c0 = bn0 + (w & 1) * 32 + ni * 8 + (lane & 3) * 2;
            float* a = acc[mi][ni];
            if (MODE == 1) {
                float b0 = bias1[c0] + bias2[c0], b1 = bias1[c0 + 1] + bias2[c0 + 1];
                *(float2*)&g_base[(size_t)r0 * 4096 + c0]       = make_float2(a[0] + b0, a[1] + b1);
                *(float2*)&g_base[(size_t)(r0 + 8) * 4096 + c0] = make_float2(a[2] + b0, a[3] + b1);
            } else {
                float b0 = bias1[c0], b1 = bias1[c0 + 1];
                float v0 = tanhf(a[0] + b0), v1 = tanhf(a[1] + b1);
                float v2 = tanhf(a[2] + b0), v3 = tanhf(a[3] + b1);
                if (MODE == 2) {
                    __half h0, l0, h1, l1;
                    __half2 hh, ll;
                    f16split(v0, h0, l0); f16split(v1, h1, l1);
                    hh.x = h0; hh.y = h1; ll.x = l0; ll.y = l1;
                    *(__half2*)&g_h_hi[0][(size_t)r0 * 1024 + c0] = hh;
                    *(__half2*)&g_h_lo[0][(size_t)r0 * 1024 + c0] = ll;
                    f16split(v2, h0, l0); f16split(v3, h1, l1);
                    hh.x = h0; hh.y = h1; ll.x = l0; ll.y = l1;
                    *(__half2*)&g_h_hi[0][(size_t)(r0 + 8) * 1024 + c0] = hh;
                    *(__half2*)&g_h_lo[0][(size_t)(r0 + 8) * 1024 + c0] = ll;
                } else {
                    g_m[(size_t)r0 * 1024 + c0]           = v0;
                    g_m[(size_t)r0 * 1024 + c0 + 1]       = v1;
                    g_m[(size_t)(r0 + 8) * 1024 + c0]     = v2;
                    g_m[(size_t)(r0 + 8) * 1024 + c0 + 1] = v3;
                }
            }
        }
    }
}

// ---------------- K4: fused step kernel, balanced 296-CTA grid -----------
// grid (74, 4), 128 threads, 3 CTAs/SM (smem 61440). One launch per step t:
//   x < 64 : GATES role, step t. Tile 64 rows x [i|f|g|o]x16 h-cols, K=1152.
//            2-term (A hi+lo x B hi). Verbatim R14 path.
//   x >= 64: FC role, step tf = t-1. Tile 128 rows x 64 cols, K=1024.
//            1-term, warp m64xn32 (mi=4). n-tile=(x-64)*2+(y>>1), m=(y&1).
// 296 CTAs = 2 x 148 -> exactly 2 resident CTAs per SM (perfect balance).
// Stage layout both roles: 15360 B x 4 stages.
//   gates: Ahi@0(5120) Alo@5120 Bhi@10240(5120)
//   fc:    Ahi@0(10240)           Bhi@10240(5120)
__global__ void __launch_bounds__(128, 3) step_fused(
    const float* __restrict__ bfc, const int* __restrict__ length,
    float* __restrict__ out, int t)
{
    extern __shared__ char smem[];
    const uint32_t smb = smem_u32(smem);
    const int tid = threadIdx.x, lane = tid & 31, w = tid >> 5;
    const int tf = t - 1;

    if (blockIdx.x < 64) {
        // ================= GATES role (R14-verbatim) =================
        if (t >= Tc) return;
        const int bm0 = blockIdx.y * 64;
        if (t >= length[bm0]) return;
        const int bn0h = blockIdx.x * 16;

        const __half* h_in_hi = g_h_hi[t & 1];
        const __half* h_in_lo = g_h_lo[t & 1];

        float acc[2][4][4];
        #pragma unroll
        for (int a = 0; a < 2; ++a)
            #pragma unroll
            for (int b = 0; b < 4; ++b)
                #pragma unroll
                for (int c = 0; c < 4; ++c) acc[a][b][c] = 0.0f;

        auto load_stage = [&](int st, int k0) {
            uint32_t sb = smb + (uint32_t)st * 15360u;
            #pragma unroll
            for (int s = 0; s < 2; ++s) {                 // A hi+lo
                int slot = tid + s * 128;
                int r = slot >> 2, ch = slot & 3, k = k0 + ch * 8;
                const __half *ah, *al;
                if (k >= 1024) {
                    size_t off = ((size_t)(bm0 + r) * Tc + t) * Lc + (k - 1024);
                    ah = g_lab_hi + off; al = g_lab_lo + off;
                } else {
                    size_t off = (size_t)(bm0 + r) * 1024 + k;
                    ah = h_in_hi + off; al = h_in_lo + off;
                }
                uint32_t so = (uint32_t)(r * 80 + ch * 16);
                cpasync16(sb + so, ah);
                cpasync16(sb + 5120u + so, al);
            }
            #pragma unroll
            for (int s = 0; s < 2; ++s) {                 // B hi
                int slot = tid + s * 128;
                int r = slot >> 2, ch = slot & 3, k = k0 + ch * 8;
                int grow = (r >> 4) * 1024 + bn0h + (r & 15);
                const __half* bh;
                if (k >= 1024) bh = g_Wlab + (size_t)grow * 128 + (k - 1024);
                else           bh = g_Whh + (size_t)grow * 1024 + k;
                uint32_t so = (uint32_t)(r * 80 + ch * 16);
                cpasync16(sb + 10240u + so, bh);
            }
        };

        load_stage(0, 0);  CP_COMMIT();
        load_stage(1, 32); CP_COMMIT();

        const uint32_t aOff = (uint32_t)(((w >> 1) * 32 + (lane & 15)) * 80 + (lane >> 4) * 16);
        const uint32_t bOff = (uint32_t)(((w & 1) * 32 + (lane & 7)) * 80 + ((lane >> 3) & 1) * 16);

        for (int it = 0; it < 36; ++it) {
            if (it + 2 < 36) load_stage((it + 2) & 3, (it + 2) * 32);
            CP_COMMIT();
            CP_WAIT2();
            __syncthreads();
            uint32_t sb = smb + (uint32_t)(it & 3) * 15360u;
            #pragma unroll
            for (int kh = 0; kh < 2; ++kh) {
                uint32_t afh[2][4], afl[2][4], bfh[4][2];
                #pragma unroll
                for (int mi = 0; mi < 2; ++mi) {
                    uint32_t ad = sb + aOff + (uint32_t)(mi * 1280 + kh * 32);
                    ldsm4(afh[mi], ad);
                    ldsm4(afl[mi], ad + 5120u);
                }
                #pragma unroll
                for (int ni = 0; ni < 4; ++ni) {
                    uint32_t bd = sb + 10240u + bOff + (uint32_t)(ni * 640 + kh * 32);
                    ldsm2(bfh[ni], bd);
                }
                #pragma unroll
                for (int mi = 0; mi < 2; ++mi)
                    #pragma unroll
                    for (int ni = 0; ni < 4; ++ni)
                        mma_f16(acc[mi][ni], afh[mi], bfh[ni]);
                #pragma unroll
                for (int mi = 0; mi < 2; ++mi)
                    #pragma unroll
                    for (int ni = 0; ni < 4; ++ni)
                        mma_f16(acc[mi][ni], afl[mi], bfh[ni]);
            }
        }
        __syncthreads();   // close skew before smem reuse (staging)

        // ---- stage 64x64 gate tile to smem (stride 68 floats) ----
        float* stg = (float*)smem;
        #pragma unroll
        for (int mi = 0; mi < 2; ++mi) {
            int r0 = (w >> 1) * 32 + mi * 16 + (lane >> 2);
            #pragma unroll
            for (int ni = 0; ni < 4; ++ni) {
                int c0 = (w & 1) * 32 + ni * 8 + (lane & 3) * 2;
                float* a = acc[mi][ni];
                *(float2*)&stg[r0 * 68 + c0]       = make_float2(a[0], a[1]);
                *(float2*)&stg[(r0 + 8) * 68 + c0] = make_float2(a[2], a[3]);
            }
        }
        __syncthreads();

        // ---- LSTM cell update (h ping-pong write) ----
        __half* h_out_hi = g_h_hi[(t + 1) & 1];
        __half* h_out_lo = g_h_lo[(t + 1) & 1];
        int nl = tid & 15;
        int rg = tid >> 4;
        int n = bn0h + nl;
        #pragma unroll
        for (int j = 0; j < 8; ++j) {
            int r = rg * 8 + j;
            int row = bm0 + r;
            float iv = stg[r * 68 + nl];
            float fv = stg[r * 68 + 16 + nl];
            float gv = stg[r * 68 + 32 + nl];
            float ov = stg[r * 68 + 48 + nl];
            size_t bidx = (size_t)row * 4096;
            iv += g_base[bidx + n];
            fv += g_base[bidx + 1024 + n];
            gv += g_base[bidx + 2048 + n];
            ov += g_base[bidx + 3072 + n];
            size_t hidx = (size_t)row * 1024 + n;
            float m = sigmoidf_(fv) * g_m[hidx] + sigmoidf_(iv) * tanhf(gv);
            g_m[hidx] = m;
            float h = sigmoidf_(ov) * tanhf(m);
            __half hh, hl;
            f16split(h, hh, hl);
            h_out_hi[hidx] = hh;
            h_out_lo[hidx] = hl;
        }
    } else {
        // ================= FC role: 128x64 tile, 1-term =================
        if (tf < 0) return;
        const int bm0 = (blockIdx.y & 1) * 128;
        if (tf >= length[bm0]) return;       // dead: output pre-zeroed
        const int bn0f = ((blockIdx.x - 64) * 2 + (blockIdx.y >> 1)) * 64;

        const __half* h_in_hi = g_h_hi[t & 1];

        float acc[4][4][4];
        #pragma unroll
        for (int a = 0; a < 4; ++a)
            #pragma unroll
            for (int b = 0; b < 4; ++b)
                #pragma unroll
                for (int c = 0; c < 4; ++c) acc[a][b][c] = 0.0f;

        auto load_stage = [&](int st, int k0) {
            uint32_t sb = smb + (uint32_t)st * 15360u;
            #pragma unroll
            for (int s = 0; s < 4; ++s) {                 // A hi: 128 rows
                int slot = tid + s * 128;
                int r = slot >> 2, ch = slot & 3, k = k0 + ch * 8;
                size_t off = (size_t)(bm0 + r) * 1024 + k;
                cpasync16(sb + (uint32_t)(r * 80 + ch * 16), h_in_hi + off);
            }
            #pragma unroll
            for (int s = 0; s < 2; ++s) {                 // B hi: 64 rows
                int slot = tid + s * 128;
                int r = slot >> 2, ch = slot & 3, k = k0 + ch * 8;
                size_t off = (size_t)(bn0f + r) * 1024 + k;
                cpasync16(sb + 10240u + (uint32_t)(r * 80 + ch * 16), g_Wfc + off);
            }
        };

        load_stage(0, 0);  CP_COMMIT();
        load_stage(1, 32); CP_COMMIT();

        const uint32_t aOff = (uint32_t)(((w >> 1) * 64 + (lane & 15)) * 80 + (lane >> 4) * 16);
        const uint32_t bOff = (uint32_t)(((w & 1) * 32 + (lane & 7)) * 80 + ((lane >> 3) & 1) * 16);

        for (int it = 0; it < 32; ++it) {
            if (it + 2 < 32) load_stage((it + 2) & 3, (it + 2) * 32);
            CP_COMMIT();
            CP_WAIT2();
            __syncthreads();
            uint32_t sb = smb + (uint32_t)(it & 3) * 15360u;
            #pragma unroll
            for (int kh = 0; kh < 2; ++kh) {
                uint32_t afh[4][4], bfh[4][2];
                #pragma unroll
                for (int mi = 0; mi < 4; ++mi) {
                    uint32_t ad = sb + aOff + (uint32_t)(mi * 1280 + kh * 32);
                    ldsm4(afh[mi], ad);
                }
                #pragma unroll
                for (int ni = 0; ni < 4; ++ni) {
                    uint32_t bd = sb + 10240u + bOff + (uint32_t)(ni * 640 + kh * 32);
                    ldsm2(bfh[ni], bd);
                }
                #pragma unroll
                for (int mi = 0; mi < 4; ++mi)
                    #pragma unroll
                    for (int ni = 0; ni < 4; ++ni)
                        mma_f16(acc[mi][ni], afh[mi], bfh[ni]);
            }
        }

        // ---- fc epilogue for step tf ----
        float* lab  = out;
        float* top  = out  + (size_t)Bb * Tc * Lc;
        float* temp = top  + (size_t)Bb * Tc * Hc;
        float* stop = temp + (size_t)Bb * Tc;
        #pragma unroll
        for (int mi = 0; mi < 4; ++mi) {
            int r0 = bm0 + (w >> 1) * 64 + mi * 16 + (lane >> 2);
            #pragma unroll
            for (int ni = 0; ni < 4; ++ni) {
                int c0 = bn0f + (w & 1) * 32 + ni * 8 + (lane & 3) * 2;
                float* a = acc[mi][ni];
                #pragma unroll
                for (int half = 0; half < 2; ++half) {
                    int r = r0 + half * 8;
                    float mask = (tf < length[r]) ? 1.0f : 0.0f;
                    size_t bt = (size_t)r * Tc + tf;
                    #pragma unroll
                    for (int j = 0; j < 2; ++j) {
                        int n = c0 + j;
                        if (n < FCOUT) {
                            float v = fmaxf(a[half * 2 + j] + bfc[n], 0.0f);
                            if (n < Lc)            lab[bt * Lc + n]        = v * mask;
                            else if (n < Lc + Hc)  top[bt * Hc + (n - Lc)] = v * mask;
                            else if (n == Lc + Hc) temp[bt]                = expf(v) * mask;
                            else                   stop[bt]                = sigmoidf_(v) * mask;
                        }
                    }
                }
            }
        }
    }
}

// ---------------- launch -------------------------------------------------
#define SMEM_MMA 61440

extern "C" void kernel_launch(void* const* d_in, const int* in_sizes, int n_in,
                              void* d_out, int out_size)
{
    const float* image  = (const float*)d_in[0];
    const float* label  = (const float*)d_in[1];
    const int*   length = (const int*)  d_in[2];
    const float* W_h    = (const float*)d_in[3];
    const float* b_h    = (const float*)d_in[4];
    const float* W_m    = (const float*)d_in[5];
    const float* b_m    = (const float*)d_in[6];
    const float* W_ih   = (const float*)d_in[7];
    const float* W_hh   = (const float*)d_in[8];
    const float* b_ih   = (const float*)d_in[9];
    const float* b_hh   = (const float*)d_in[10];
    const float* W_fc   = (const float*)d_in[11];
    const float* b_fc   = (const float*)d_in[12];
    float* out = (float*)d_out;

    static bool attr_done = false;
    if (!attr_done) {
        cudaFuncSetAttribute(mma_big<1>, cudaFuncAttributeMaxDynamicSharedMemorySize, SMEM_MMA);
        cudaFuncSetAttribute(mma_big<2>, cudaFuncAttributeMaxDynamicSharedMemorySize, SMEM_MMA);
        cudaFuncSetAttribute(mma_big<3>, cudaFuncAttributeMaxDynamicSharedMemorySize, SMEM_MMA);
        cudaFuncSetAttribute(step_fused, cudaFuncAttributeMaxDynamicSharedMemorySize, SMEM_MMA);
        attr_done = true;
    }

    int n4 = out_size / 4;
    zero_out<<<(n4 + 255) / 256, 256>>>((float4*)out, n4);
    mean_part<<<dim3(Bb, 7), 256>>>(image);
    mean_reduce<<<(Bb * Ec / 4) / 256, 256>>>();
    split_all<<<(C6 + 255) / 256, 256>>>(W_h, W_m, W_ih, W_hh, W_fc, label);

    mma_big<1><<<dim3(64, 4), 128, SMEM_MMA>>>(b_ih, b_hh);
    mma_big<2><<<dim3(16, 4), 128, SMEM_MMA>>>(b_h, nullptr);
    mma_big<3><<<dim3(16, 4), 128, SMEM_MMA>>>(b_m, nullptr);

    // step t: gates_t (x<64) + fc_{t-1} (x 64..73); t=Tc runs fc_{Tc-1} only
    for (int t = 0; t <= Tc; ++t) {
        step_fused<<<dim3(74, 4), 128, SMEM_MMA>>>(b_fc, length, out, t);
    }
}